// round 11
// baseline (speedup 1.0000x reference)
#include <cuda_runtime.h>
#include <cuda_fp16.h>
#include <math.h>
#include <stdint.h>

#define BATCH 4
#define CH    512
#define HWN   4096
#define NGROUPS 32
#define CPG   16

#define TK 32
#define STAGES 3

// ---------------- scratch (device globals; allocation-free) ----------------
__device__ __half g_h [(size_t)BATCH * CH * HWN];   // h   [ch][hw]
__device__ __half g_qt[(size_t)BATCH * CH * HWN];   // q^T [hw][ch]
__device__ __half g_kt[(size_t)BATCH * CH * HWN];   // k^T [hw][ch]
__device__ __half g_v [(size_t)BATCH * CH * HWN];   // v   [ch][hw]
__device__ __half g_ot[(size_t)BATCH * CH * HWN];   // o^T [hw][ch]
__device__ __half g_w [4 * CH * CH];                // fp16 weights q,k,v,o

// ---------------- helpers ----------------
__device__ __forceinline__ uint32_t smem_u32(const void* p) {
    return (uint32_t)__cvta_generic_to_shared(p);
}
__device__ __forceinline__ void cp16(uint32_t dst, const void* src) {
    asm volatile("cp.async.cg.shared.global [%0], [%1], 16;\n" :: "r"(dst), "l"(src));
}
__device__ __forceinline__ void cp_commit() {
    asm volatile("cp.async.commit_group;\n");
}
template<int N> __device__ __forceinline__ void cp_wait() {
    asm volatile("cp.async.wait_group %0;\n" :: "n"(N));
}
__device__ __forceinline__ void ldmx4(uint32_t* r, uint32_t a) {
    asm volatile("ldmatrix.sync.aligned.m8n8.x4.shared.b16 {%0,%1,%2,%3}, [%4];"
        : "=r"(r[0]), "=r"(r[1]), "=r"(r[2]), "=r"(r[3]) : "r"(a));
}
__device__ __forceinline__ void ldmx4t(uint32_t* r, uint32_t a) {
    asm volatile("ldmatrix.sync.aligned.m8n8.x4.trans.shared.b16 {%0,%1,%2,%3}, [%4];"
        : "=r"(r[0]), "=r"(r[1]), "=r"(r[2]), "=r"(r[3]) : "r"(a));
}
__device__ __forceinline__ void mma_f16(float* d, const uint32_t* a, const uint32_t* b) {
    asm volatile(
        "mma.sync.aligned.m16n8k16.row.col.f32.f16.f16.f32 "
        "{%0,%1,%2,%3}, {%4,%5,%6,%7}, {%8,%9}, {%0,%1,%2,%3};"
        : "+f"(d[0]), "+f"(d[1]), "+f"(d[2]), "+f"(d[3])
        : "r"(a[0]), "r"(a[1]), "r"(a[2]), "r"(a[3]), "r"(b[0]), "r"(b[1]));
}

// ---------------- weight staging ----------------
__global__ void cvt_w_kernel(const float* __restrict__ w0, const float* __restrict__ w1,
                             const float* __restrict__ w2, const float* __restrict__ w3,
                             __half* __restrict__ dst) {
    const int n = CH * CH;
    const float* srcs[4] = {w0, w1, w2, w3};
    for (int idx = blockIdx.x * blockDim.x + threadIdx.x; idx < 4 * n;
         idx += gridDim.x * blockDim.x)
        dst[idx] = __float2half(srcs[idx / n][idx % n]);
}

// ---------------- GroupNorm (fp32 in, fp16 out, [ch][hw]) ----------------
__global__ void gn_kernel(const float* __restrict__ x,
                          const float* __restrict__ gamma,
                          const float* __restrict__ beta,
                          __half* __restrict__ h) {
    const int b = blockIdx.x / NGROUPS;
    const int g = blockIdx.x % NGROUPS;
    const int n = CPG * HWN;
    const float* xp = x + ((size_t)b * CH + (size_t)g * CPG) * HWN;
    __half*      hp = h + ((size_t)b * CH + (size_t)g * CPG) * HWN;

    float s = 0.f, ss = 0.f;
    for (int i = threadIdx.x; i < n; i += 256) {
        float v = xp[i];
        s += v; ss += v * v;
    }
    __shared__ float sh1[256], sh2[256];
    sh1[threadIdx.x] = s; sh2[threadIdx.x] = ss;
    __syncthreads();
    for (int o = 128; o > 0; o >>= 1) {
        if (threadIdx.x < o) {
            sh1[threadIdx.x] += sh1[threadIdx.x + o];
            sh2[threadIdx.x] += sh2[threadIdx.x + o];
        }
        __syncthreads();
    }
    const float mean = sh1[0] / (float)n;
    const float var  = sh2[0] / (float)n - mean * mean;
    const float inv  = rsqrtf(var + 1e-6f);

    for (int i = threadIdx.x; i < n; i += 256) {
        int c = g * CPG + i / HWN;
        hp[i] = __float2half((xp[i] - mean) * inv * gamma[c] + beta[c]);
    }
}

// ---------------- FP16 GEMM (projections), 3-stage cp.async ----------------
// C[m,n] = op(A)*op(B); ATRANS: A stored [K,M]; BTRANS: B stored [N,K]
// EPI: 1 +bias[row] (half out), 2 +bias[row]+res (float out), 7 +bias[col] (half out)
template<int BM, int BN, bool ATRANS, bool BTRANS, int EPI>
__global__ __launch_bounds__(256)
void gemm_f16(const __half* __restrict__ Ag, const __half* __restrict__ Bg,
              void* __restrict__ Cg,
              const float* __restrict__ bias, const float* __restrict__ res,
              int K, int lda, int ldb, int ldc,
              size_t strA, size_t strB, size_t strC)
{
    extern __shared__ __half smem[];
    constexpr int SA = ATRANS ? (BM + 8) : (TK + 8);
    constexpr int SB = BTRANS ? (TK + 8) : (BN + 8);
    constexpr int SZA = ATRANS ? TK * SA : BM * SA;
    constexpr int SZB = BTRANS ? BN * SB : TK * SB;
    constexpr int STG = SZA + SZB;
    constexpr int NI = 4;                  // warp tile 64 x 32
    constexpr int NJ = 4;
    constexpr int ACH = ATRANS ? BM / 8 : TK / 8;
    constexpr int ANR = ATRANS ? TK : BM;
    constexpr int BCH = BTRANS ? TK / 8 : BN / 8;
    constexpr int BNR = BTRANS ? BN : TK;

    const int bz = blockIdx.z;
    const int m0 = blockIdx.y * BM;
    const int n0 = blockIdx.x * BN;
    const __half* A = Ag + (size_t)bz * strA;
    const __half* B = Bg + (size_t)bz * strB;
    const size_t coff = (size_t)bz * strC;
    const float* R = (EPI == 2) ? (res + coff) : nullptr;

    const int tid  = threadIdx.x;
    const int wid  = tid >> 5;
    const int lane = tid & 31;
    const int gid  = lane >> 2;
    const int tig  = lane & 3;
    const int wm   = (wid >> 2) * 64;
    const int wn   = (wid & 3) * 32;
    const int lq   = lane >> 3;
    const int lr   = lane & 7;

    auto copy_tile = [&](int kt, int st) {
        __half* as = smem + st * STG;
        __half* bs = as + SZA;
        const int k0 = kt * TK;
        #pragma unroll
        for (int i = 0; i < ANR * ACH / 256; i++) {
            int idx = tid + i * 256;
            int r = idx / ACH, c = idx % ACH;
            if (ATRANS)
                cp16(smem_u32(as + r * SA + c * 8), A + (size_t)(k0 + r) * lda + m0 + c * 8);
            else
                cp16(smem_u32(as + r * SA + c * 8), A + (size_t)(m0 + r) * lda + k0 + c * 8);
        }
        #pragma unroll
        for (int i = 0; i < BNR * BCH / 256; i++) {
            int idx = tid + i * 256;
            int r = idx / BCH, c = idx % BCH;
            if (BTRANS)
                cp16(smem_u32(bs + r * SB + c * 8), B + (size_t)(n0 + r) * ldb + k0 + c * 8);
            else
                cp16(smem_u32(bs + r * SB + c * 8), B + (size_t)(k0 + r) * ldb + n0 + c * 8);
        }
    };

    float acc[NI][NJ][4] = {};
    const int KT = K / TK;

    copy_tile(0, 0); cp_commit();
    copy_tile(1, 1); cp_commit();

    for (int kt = 0; kt < KT; kt++) {
        cp_wait<1>();
        __syncthreads();
        if (kt + 2 < KT) copy_tile(kt + 2, (kt + 2) % STAGES);
        cp_commit();

        const __half* as = smem + (kt % STAGES) * STG;
        const __half* bs = as + SZA;

        #pragma unroll
        for (int ks = 0; ks < 2; ks++) {
            const int kk = ks * 16;
            uint32_t a[NI][4], b[NJ / 2][4];
            #pragma unroll
            for (int i = 0; i < NI; i++) {
                const int mb = wm + i * 16;
                if (ATRANS)
                    ldmx4t(a[i], smem_u32(as + (size_t)(kk + (lq >> 1) * 8 + lr) * SA
                                             + mb + (lq & 1) * 8));
                else
                    ldmx4(a[i], smem_u32(as + (size_t)(mb + lr + (lq & 1) * 8) * SA
                                            + kk + (lq >> 1) * 8));
            }
            #pragma unroll
            for (int jj = 0; jj < NJ / 2; jj++) {
                const int nb = wn + jj * 16;
                if (BTRANS)
                    ldmx4(b[jj], smem_u32(bs + (size_t)(nb + (lq >> 1) * 8 + lr) * SB
                                             + kk + (lq & 1) * 8));
                else
                    ldmx4t(b[jj], smem_u32(bs + (size_t)(kk + (lq & 1) * 8 + lr) * SB
                                              + nb + (lq >> 1) * 8));
            }
            #pragma unroll
            for (int i = 0; i < NI; i++)
                #pragma unroll
                for (int j = 0; j < NJ; j++)
                    mma_f16(acc[i][j], a[i], &b[j >> 1][(j & 1) * 2]);
        }
    }

    __syncthreads();

    #pragma unroll
    for (int i = 0; i < NI; i++) {
        const int r0 = m0 + wm + i * 16 + gid;
        float b0v = 0.f, b1v = 0.f;
        if (EPI == 1 || EPI == 2) { b0v = bias[r0]; b1v = bias[r0 + 8]; }
        #pragma unroll
        for (int j = 0; j < NJ; j++) {
            const int c0 = n0 + wn + j * 8 + tig * 2;
            size_t i0 = (size_t)r0 * ldc + c0;
            size_t i1 = (size_t)(r0 + 8) * ldc + c0;
            float2 v0 = make_float2(acc[i][j][0], acc[i][j][1]);
            float2 v1 = make_float2(acc[i][j][2], acc[i][j][3]);
            if (EPI == 1 || EPI == 2) { v0.x += b0v; v0.y += b0v; v1.x += b1v; v1.y += b1v; }
            if (EPI == 7) {
                float c0v = bias[c0], c1v = bias[c0 + 1];
                v0.x += c0v; v0.y += c1v; v1.x += c0v; v1.y += c1v;
            }
            if (EPI == 2) {
                float2 r0v = *reinterpret_cast<const float2*>(&R[i0]);
                float2 r1v = *reinterpret_cast<const float2*>(&R[i1]);
                v0.x += r0v.x; v0.y += r0v.y; v1.x += r1v.x; v1.y += r1v.y;
                float* C = (float*)Cg + coff;
                *reinterpret_cast<float2*>(&C[i0]) = v0;
                *reinterpret_cast<float2*>(&C[i1]) = v1;
            } else {
                __half* C = (__half*)Cg + coff;
                *reinterpret_cast<__half2*>(&C[i0]) = __floats2half2_rn(v0.x, v0.y);
                *reinterpret_cast<__half2*>(&C[i1]) = __floats2half2_rn(v1.x, v1.y);
            }
        }
    }
}

// ---------------- fused flash attention ------------------------------------
// CTA: 64 Q-rows, 512 threads (16 warps). Loops 32 key-tiles of 128.
// S = Q·K^T (K-stream), P = exp(scale*S) -> smem, O += P·V (V-stream).
// Row sums kept in smem; final O normalized in-CTA. Output o^T [hw][ch].
#define QS_H  520          // Q smem row stride (halves)
#define KT_H  40           // Kt chunk row stride
#define PS_H  136          // P row stride
#define VS_H  24           // V chunk row stride
#define KT_STG (128 * KT_H)
#define VS_STG (512 * VS_H)
#define QS_OFF 0
#define KT_OFF (64 * QS_H)                    // 33280 halves
#define PS_OFF (KT_OFF + 3 * KT_STG)          // +15360
#define VS_OFF (PS_OFF + 64 * PS_H)           // +8704
#define LS_OFF (VS_OFF + 3 * VS_STG)          // +36864 (halves); L as float after
#define FL_SMEM ((LS_OFF) * 2 + 64 * 4 + 16)

__global__ __launch_bounds__(512, 1)
void flash_kernel(const __half* __restrict__ qtg, const __half* __restrict__ ktg,
                  const __half* __restrict__ vg, __half* __restrict__ otg,
                  float scale)
{
    extern __shared__ __half smem[];
    __half* QS = smem + QS_OFF;
    __half* KS = smem + KT_OFF;
    __half* PS = smem + PS_OFF;
    __half* VS = smem + VS_OFF;
    float*  LS = (float*)(smem + LS_OFF);

    const int b  = blockIdx.y;
    const int q0 = blockIdx.x * 64;
    const size_t sCH = (size_t)CH * HWN;
    const __half* qt = qtg + (size_t)b * sCH;
    const __half* kt = ktg + (size_t)b * sCH;
    const __half* v  = vg  + (size_t)b * sCH;
    __half*       ot = otg + (size_t)b * sCH;

    const int tid  = threadIdx.x;
    const int wid  = tid >> 5;
    const int lane = tid & 31;
    const int gid  = lane >> 2;
    const int tig  = lane & 3;
    const int lq   = lane >> 3;
    const int lr   = lane & 7;
    const int wmS  = (wid >> 2) * 16;     // S: 4x4 warps, tile 16x32
    const int wnS  = (wid & 3) * 32;
    const int wmP  = (wid >> 2) * 16;     // PV: 4x4 warps, tile 16x128
    const int wnP  = (wid & 3) * 128;

    if (tid < 64) LS[tid] = 0.f;

    // load Q block [64][512] into smem (k-contiguous rows)
    #pragma unroll
    for (int i = 0; i < 8; i++) {
        int idx = tid + i * 512;
        int r = idx >> 6, c = idx & 63;
        cp16(smem_u32(QS + r * QS_H + c * 8), qt + (size_t)(q0 + r) * CH + c * 8);
    }
    cp_commit();
    cp_wait<0>();
    __syncthreads();

    float accO[16][4] = {};

    for (int j = 0; j < HWN / 128; j++) {
        const int key0 = j * 128;

        // ---- S phase: S[64][128] over K=512 in 16 chunks of 32ch ----
        auto copy_kt = [&](int c, int st) {
            int r = tid >> 2, cc = tid & 3;
            cp16(smem_u32(KS + st * KT_STG + r * KT_H + cc * 8),
                 kt + (size_t)(key0 + r) * CH + c * 32 + cc * 8);
        };
        float accS[4][4] = {};
        copy_kt(0, 0); cp_commit();
        copy_kt(1, 1); cp_commit();
        for (int c = 0; c < 16; c++) {
            cp_wait<1>();
            __syncthreads();
            if (c + 2 < 16) copy_kt(c + 2, (c + 2) % 3);
            cp_commit();
            const __half* ks = KS + (c % 3) * KT_STG;
            #pragma unroll
            for (int ksb = 0; ksb < 2; ksb++) {
                const int kg = c * 32 + ksb * 16;   // global ch for Q
                const int kl = ksb * 16;            // local ch in Kt chunk
                uint32_t a[4], bb[2][4];
                ldmx4(a, smem_u32(QS + (size_t)(wmS + lr + (lq & 1) * 8) * QS_H
                                     + kg + (lq >> 1) * 8));
                #pragma unroll
                for (int jj = 0; jj < 2; jj++)
                    ldmx4(bb[jj], smem_u32(ks + (size_t)(wnS + jj * 16 + (lq >> 1) * 8 + lr) * KT_H
                                              + kl + (lq & 1) * 8));
                #pragma unroll
                for (int jq = 0; jq < 4; jq++)
                    mma_f16(accS[jq], a, &bb[jq >> 1][(jq & 1) * 2]);
            }
        }

        // ---- exp + P store + row-sum atomics ----
        {
            const int r0 = wmS + gid, r1 = r0 + 8;
            float rs0 = 0.f, rs1 = 0.f;
            #pragma unroll
            for (int jq = 0; jq < 4; jq++) {
                const int c0 = wnS + jq * 8 + tig * 2;
                float e0 = __expf(accS[jq][0] * scale);
                float e1 = __expf(accS[jq][1] * scale);
                float e2 = __expf(accS[jq][2] * scale);
                float e3 = __expf(accS[jq][3] * scale);
                rs0 += e0 + e1; rs1 += e2 + e3;
                *reinterpret_cast<__half2*>(PS + (size_t)r0 * PS_H + c0) = __floats2half2_rn(e0, e1);
                *reinterpret_cast<__half2*>(PS + (size_t)r1 * PS_H + c0) = __floats2half2_rn(e2, e3);
            }
            rs0 += __shfl_xor_sync(0xffffffffu, rs0, 1);
            rs0 += __shfl_xor_sync(0xffffffffu, rs0, 2);
            rs1 += __shfl_xor_sync(0xffffffffu, rs1, 1);
            rs1 += __shfl_xor_sync(0xffffffffu, rs1, 2);
            if (tig == 0) { atomicAdd(&LS[r0], rs0); atomicAdd(&LS[r1], rs1); }
        }
        __syncthreads();

        // ---- PV phase: O[64][512] += P[64][128] · V, 8 chunks of 16 keys ----
        auto copy_v = [&](int vc, int st) {
            #pragma unroll
            for (int i = 0; i < 2; i++) {
                int idx = tid + i * 512;
                int r = idx >> 1, cc = idx & 1;
                cp16(smem_u32(VS + st * VS_STG + r * VS_H + cc * 8),
                     v + (size_t)r * HWN + key0 + vc * 16 + cc * 8);
            }
        };
        copy_v(0, 0); cp_commit();
        copy_v(1, 1); cp_commit();
        for (int vc = 0; vc < 8; vc++) {
            cp_wait<1>();
            __syncthreads();
            if (vc + 2 < 8) copy_v(vc + 2, (vc + 2) % 3);
            cp_commit();
            const __half* vs = VS + (vc % 3) * VS_STG;
            uint32_t a[4];
            ldmx4(a, smem_u32(PS + (size_t)(wmP + lr + (lq & 1) * 8) * PS_H
                                 + vc * 16 + (lq >> 1) * 8));
            #pragma unroll
            for (int half_n = 0; half_n < 2; half_n++) {
                uint32_t bb[4][4];
                #pragma unroll
                for (int jj = 0; jj < 4; jj++)
                    ldmx4(bb[jj], smem_u32(vs + (size_t)(wnP + half_n * 64 + jj * 16
                                                         + (lq >> 1) * 8 + lr) * VS_H
                                              + (lq & 1) * 8));
                #pragma unroll
                for (int jq = 0; jq < 8; jq++)
                    mma_f16(accO[half_n * 8 + jq], a, &bb[jq >> 1][(jq & 1) * 2]);
            }
        }
        __syncthreads();   // P / L safe to rewrite next tile
    }

    // ---- normalize + write o^T [hw][ch] ----
    const int r0 = wmP + gid, r1 = r0 + 8;
    const float l0 = 1.f / LS[r0];
    const float l1 = 1.f / LS[r1];
    #pragma unroll
    for (int jq = 0; jq < 16; jq++) {
        const int c0 = wnP + jq * 8 + tig * 2;
        *reinterpret_cast<__half2*>(ot + (size_t)(q0 + r0) * CH + c0) =
            __floats2half2_rn(accO[jq][0] * l0, accO[jq][1] * l0);
        *reinterpret_cast<__half2*>(ot + (size_t)(q0 + r1) * CH + c0) =
            __floats2half2_rn(accO[jq][2] * l1, accO[jq][3] * l1);
    }
}

// ---------------- launch ----------------
extern "C" void kernel_launch(void* const* d_in, const int* in_sizes, int n_in,
                              void* d_out, int out_size) {
    const float* x        = (const float*)d_in[0];
    const float* gn_gamma = (const float*)d_in[1];
    const float* gn_beta  = (const float*)d_in[2];
    const float* wq       = (const float*)d_in[3];
    const float* bq       = (const float*)d_in[4];
    const float* wk       = (const float*)d_in[5];
    const float* bk       = (const float*)d_in[6];
    const float* wv       = (const float*)d_in[7];
    const float* bv       = (const float*)d_in[8];
    const float* wo       = (const float*)d_in[9];
    const float* bo       = (const float*)d_in[10];
    float* out = (float*)d_out;

    __half *ph, *pqt, *pkt, *pv, *pot, *pw;
    cudaGetSymbolAddress((void**)&ph,  g_h);
    cudaGetSymbolAddress((void**)&pqt, g_qt);
    cudaGetSymbolAddress((void**)&pkt, g_kt);
    cudaGetSymbolAddress((void**)&pv,  g_v);
    cudaGetSymbolAddress((void**)&pot, g_ot);
    cudaGetSymbolAddress((void**)&pw,  g_w);

    const size_t sCH = (size_t)CH * HWN;
    const float scale = 0.04419417382415922f; // 512^-0.5
    const int WS = CH * CH;

    const int smem_vp = STAGES * (128 * (TK + 8) + TK * (128 + 8)) * 2; // v proj
    const int smem_qk = STAGES * (TK * (128 + 8) + 128 * (TK + 8)) * 2; // q/k proj
    const int smem_op = STAGES * (128 * (TK + 8) + 128 * (TK + 8)) * 2; // out proj

    cudaFuncSetAttribute(gemm_f16<128, 128, false, false, 1>,
                         cudaFuncAttributeMaxDynamicSharedMemorySize, smem_vp);
    cudaFuncSetAttribute(gemm_f16<128, 128, true, true, 7>,
                         cudaFuncAttributeMaxDynamicSharedMemorySize, smem_qk);
    cudaFuncSetAttribute(gemm_f16<128, 128, false, true, 2>,
                         cudaFuncAttributeMaxDynamicSharedMemorySize, smem_op);
    cudaFuncSetAttribute(flash_kernel,
                         cudaFuncAttributeMaxDynamicSharedMemorySize, FL_SMEM);

    // 0) weights -> fp16
    cvt_w_kernel<<<256, 256>>>(wq, wk, wv, wo, pw);

    // 1) GroupNorm -> fp16 h [ch][hw]
    gn_kernel<<<BATCH * NGROUPS, 256>>>(x, gn_gamma, gn_beta, ph);

    // 2) q^T,k^T [hw][ch] = h^T · W^T  (A=h^T ATRANS, B=W BTRANS, bias per col)
    dim3 qg(CH / 128, HWN / 128, BATCH);
    gemm_f16<128, 128, true, true, 7><<<qg, 256, smem_qk>>>(
        ph, pw + 0 * WS, pqt, bq, nullptr, CH, HWN, CH, CH, sCH, 0, sCH);
    gemm_f16<128, 128, true, true, 7><<<qg, 256, smem_qk>>>(
        ph, pw + 1 * WS, pkt, bk, nullptr, CH, HWN, CH, CH, sCH, 0, sCH);
    //    v [ch][hw] = Wv · h  (bias per row)
    dim3 vg(HWN / 128, CH / 128, BATCH);
    gemm_f16<128, 128, false, false, 1><<<vg, 256, smem_vp>>>(
        pw + 2 * WS, ph, pv, bv, nullptr, CH, CH, HWN, HWN, 0, sCH, sCH);

    // 3) fused attention -> o^T [hw][ch]
    dim3 fg(HWN / 64, BATCH);
    flash_kernel<<<fg, 512, FL_SMEM>>>(pqt, pkt, pv, pot, scale);

    // 4) out [ch][hw] = Wo · o + bias + x  (A=Wo, B=o^T BTRANS, f32 out)
    dim3 og(HWN / 128, CH / 128, BATCH);
    gemm_f16<128, 128, false, true, 2><<<og, 256, smem_op>>>(
        pw + 3 * WS, pot, out, bo, x, CH, CH, CH, HWN, 0, sCH, sCH);
}

// round 12
// speedup vs baseline: 1.4711x; 1.4711x over previous
#include <cuda_runtime.h>
#include <cuda_fp16.h>
#include <math.h>
#include <stdint.h>

#define BATCH 4
#define CH    512
#define HWN   4096
#define NGROUPS 32
#define CPG   16

#define TM 128
#define TN 128
#define TK 32
#define STAGES 3

// ---------------- scratch (device globals; allocation-free) ----------------
__device__ __half g_h[(size_t)BATCH * CH * HWN];
__device__ __half g_qkv[3 * (size_t)BATCH * CH * HWN];   // q,k,v contiguous
__device__ __half g_o[(size_t)BATCH * CH * HWN];
__device__ __half g_s[(size_t)BATCH * HWN * HWN];   // unnormalized exp(S)
__device__ float  g_l[(size_t)BATCH * HWN];         // row sums
__device__ __half g_w[4 * CH * CH];                 // fp16 weights q,k,v,o
__device__ float  g_bias[3 * CH];                   // staged biases q,k,v
__device__ float  g_stats[BATCH * NGROUPS * 2];     // GN sum / sumsq

// ---------------- helpers ----------------
__device__ __forceinline__ uint32_t smem_u32(const void* p) {
    return (uint32_t)__cvta_generic_to_shared(p);
}
__device__ __forceinline__ void cp16(uint32_t dst, const void* src) {
    asm volatile("cp.async.cg.shared.global [%0], [%1], 16;\n" :: "r"(dst), "l"(src));
}
__device__ __forceinline__ void cp_commit() {
    asm volatile("cp.async.commit_group;\n");
}
template<int N> __device__ __forceinline__ void cp_wait() {
    asm volatile("cp.async.wait_group %0;\n" :: "n"(N));
}
__device__ __forceinline__ void ldmx4(uint32_t* r, uint32_t a) {
    asm volatile("ldmatrix.sync.aligned.m8n8.x4.shared.b16 {%0,%1,%2,%3}, [%4];"
        : "=r"(r[0]), "=r"(r[1]), "=r"(r[2]), "=r"(r[3]) : "r"(a));
}
__device__ __forceinline__ void ldmx4t(uint32_t* r, uint32_t a) {
    asm volatile("ldmatrix.sync.aligned.m8n8.x4.trans.shared.b16 {%0,%1,%2,%3}, [%4];"
        : "=r"(r[0]), "=r"(r[1]), "=r"(r[2]), "=r"(r[3]) : "r"(a));
}
__device__ __forceinline__ void mma_f16(float* d, const uint32_t* a, const uint32_t* b) {
    asm volatile(
        "mma.sync.aligned.m16n8k16.row.col.f32.f16.f16.f32 "
        "{%0,%1,%2,%3}, {%4,%5,%6,%7}, {%8,%9}, {%0,%1,%2,%3};"
        : "+f"(d[0]), "+f"(d[1]), "+f"(d[2]), "+f"(d[3])
        : "r"(a[0]), "r"(a[1]), "r"(a[2]), "r"(a[3]), "r"(b[0]), "r"(b[1]));
}

// ---------------- weight/bias staging ----------------
__global__ void cvt_w_kernel(const float* __restrict__ w0, const float* __restrict__ w1,
                             const float* __restrict__ w2, const float* __restrict__ w3,
                             const float* __restrict__ b0, const float* __restrict__ b1,
                             const float* __restrict__ b2,
                             __half* __restrict__ dst, float* __restrict__ bdst) {
    const int n = CH * CH;
    const float* srcs[4] = {w0, w1, w2, w3};
    for (int idx = blockIdx.x * blockDim.x + threadIdx.x; idx < 4 * n;
         idx += gridDim.x * blockDim.x)
        dst[idx] = __float2half(srcs[idx / n][idx % n]);
    if (blockIdx.x == 0) {
        const float* bs[3] = {b0, b1, b2};
        for (int idx = threadIdx.x; idx < 3 * CH; idx += blockDim.x)
            bdst[idx] = bs[idx / CH][idx % CH];
    }
}

// ---------------- GroupNorm pass 1: partial stats -> atomics ---------------
// 8 blocks per (batch,group); each reduces 8192 elems (2048 float4)
__global__ void gn_stats_kernel(const float* __restrict__ x, float* __restrict__ stats) {
    const int bg   = blockIdx.x >> 3;
    const int part = blockIdx.x & 7;
    const float4* xp = reinterpret_cast<const float4*>(x) + (size_t)bg * 16384 + part * 2048;
    const int tid = threadIdx.x;

    float s = 0.f, ss = 0.f;
    #pragma unroll
    for (int i = 0; i < 8; i++) {
        float4 v = xp[tid + i * 256];
        s  += v.x + v.y + v.z + v.w;
        ss += v.x * v.x + v.y * v.y + v.z * v.z + v.w * v.w;
    }
    __shared__ float sh1[256], sh2[256];
    sh1[tid] = s; sh2[tid] = ss;
    __syncthreads();
    for (int o = 128; o > 0; o >>= 1) {
        if (tid < o) { sh1[tid] += sh1[tid + o]; sh2[tid] += sh2[tid + o]; }
        __syncthreads();
    }
    if (tid == 0) {
        atomicAdd(&stats[bg * 2],     sh1[0]);
        atomicAdd(&stats[bg * 2 + 1], sh2[0]);
    }
}

// ---------------- GroupNorm pass 2: normalize (fp32 in, fp16 out) ----------
__global__ void gn_apply_kernel(const float* __restrict__ x,
                                const float* __restrict__ gamma,
                                const float* __restrict__ beta,
                                const float* __restrict__ stats,
                                __half* __restrict__ h) {
    const size_t f = (size_t)blockIdx.x * blockDim.x + threadIdx.x;  // float4 index
    const int per_b = CH * HWN / 4;                // 524288
    const int b = (int)(f / per_b);
    const int r = (int)(f % per_b);
    const int c = r / (HWN / 4);
    const int bg = b * NGROUPS + c / CPG;

    const float sum = stats[bg * 2], sumsq = stats[bg * 2 + 1];
    const float mean = sum * (1.f / 65536.f);
    const float var  = sumsq * (1.f / 65536.f) - mean * mean;
    const float inv  = rsqrtf(var + 1e-6f);
    const float sc = gamma[c] * inv;
    const float of = beta[c] - mean * sc;

    float4 v = reinterpret_cast<const float4*>(x)[f];
    __half2 h01 = __floats2half2_rn(v.x * sc + of, v.y * sc + of);
    __half2 h23 = __floats2half2_rn(v.z * sc + of, v.w * sc + of);
    uint2 pk;
    pk.x = *reinterpret_cast<uint32_t*>(&h01);
    pk.y = *reinterpret_cast<uint32_t*>(&h23);
    reinterpret_cast<uint2*>(h)[f] = pk;
}

// ---------------- FP16 tensor-core GEMM, 3-stage cp.async + ldmatrix -------
// C[m,n] = op(A)*op(B); ATRANS: A stored [K,M]; BTRANS: B stored [N,K]
// EPI: 1 +bias (half out), 2 +bias+res (float out),
//      4 exp(scale*acc)+rowsum (half out), 5 col-normalize by Lsum (half out),
//      6 merged QKV: z=(proj,batch), +bias (half out)
template<bool ATRANS, bool BTRANS, int EPI>
__global__ __launch_bounds__(256)
void gemm_f16(const __half* __restrict__ Ag, const __half* __restrict__ Bg,
              void* __restrict__ Cg,
              const float* __restrict__ bias, const float* __restrict__ res,
              float* __restrict__ Lsum,
              int K, int lda, int ldb, int ldc,
              size_t strA, size_t strB, size_t strC, float scale)
{
    extern __shared__ __half smem[];
    constexpr int SA = ATRANS ? (TM + 8) : (TK + 8);   // halves
    constexpr int SB = BTRANS ? (TK + 8) : (TN + 8);
    constexpr int SZA = ATRANS ? TK * SA : TM * SA;
    constexpr int SZB = BTRANS ? TN * SB : TK * SB;
    constexpr int STG = SZA + SZB;
    constexpr bool HAS_BIAS = (EPI == 1 || EPI == 2 || EPI == 6);

    const int zz = blockIdx.z;
    const int proj = (EPI == 6) ? (zz >> 2) : 0;
    const int bz   = (EPI == 6) ? (zz & 3)  : zz;
    const int m0 = blockIdx.y * TM;
    const int n0 = blockIdx.x * TN;
    const __half* A = Ag + ((EPI == 6) ? (size_t)proj * CH * CH : (size_t)bz * strA);
    const __half* B = Bg + (size_t)bz * strB;
    const size_t coff = (EPI == 6) ? ((size_t)proj * BATCH + bz) * strC
                                   : (size_t)bz * strC;
    const float* R = (EPI == 2) ? (res + coff) : nullptr;
    const float* Bi = HAS_BIAS ? (bias + ((EPI == 6) ? proj * CH : 0)) : nullptr;
    float* L = (EPI == 4 || EPI == 5) ? (Lsum + (size_t)bz * HWN) : nullptr;

    const int tid  = threadIdx.x;
    const int wid  = tid >> 5;
    const int lane = tid & 31;
    const int gid  = lane >> 2;
    const int tig  = lane & 3;
    const int wm   = (wid >> 2) * 64;
    const int wn   = (wid & 3) * 32;
    const int lq   = lane >> 3;    // ldmatrix quadrant
    const int lr   = lane & 7;     // ldmatrix row

    auto copy_tile = [&](int kt, int st) {
        __half* as = smem + st * STG;
        __half* bs = as + SZA;
        const int k0 = kt * TK;
        #pragma unroll
        for (int i = 0; i < 2; i++) {
            int idx = tid + i * 256;
            if (ATRANS) {            // A[K,M], m contiguous: 32 rows x 16 chunks
                int k = idx >> 4, c = idx & 15;
                cp16(smem_u32(as + k * SA + c * 8), A + (size_t)(k0 + k) * lda + m0 + c * 8);
            } else {                 // A[M,K]: 128 rows x 4 chunks
                int m = idx >> 2, c = idx & 3;
                cp16(smem_u32(as + m * SA + c * 8), A + (size_t)(m0 + m) * lda + k0 + c * 8);
            }
        }
        #pragma unroll
        for (int i = 0; i < 2; i++) {
            int idx = tid + i * 256;
            if (BTRANS) {            // B[N,K]: 128 rows x 4 chunks
                int n = idx >> 2, c = idx & 3;
                cp16(smem_u32(bs + n * SB + c * 8), B + (size_t)(n0 + n) * ldb + k0 + c * 8);
            } else {                 // B[K,N]: 32 rows x 16 chunks
                int k = idx >> 4, c = idx & 15;
                cp16(smem_u32(bs + k * SB + c * 8), B + (size_t)(k0 + k) * ldb + n0 + c * 8);
            }
        }
    };

    float acc[4][4][4] = {};
    const int KT = K / TK;

    copy_tile(0, 0); cp_commit();
    copy_tile(1, 1); cp_commit();

    for (int kt = 0; kt < KT; kt++) {
        cp_wait<1>();
        __syncthreads();
        if (kt + 2 < KT) copy_tile(kt + 2, (kt + 2) % STAGES);
        cp_commit();

        const __half* as = smem + (kt % STAGES) * STG;
        const __half* bs = as + SZA;

        #pragma unroll
        for (int ks = 0; ks < 2; ks++) {
            const int kk = ks * 16;
            uint32_t a[4][4], b[2][4];
            #pragma unroll
            for (int i = 0; i < 4; i++) {
                const int mb = wm + i * 16;
                if (ATRANS) {
                    uint32_t addr = smem_u32(as + (size_t)(kk + (lq >> 1) * 8 + lr) * SA
                                                + mb + (lq & 1) * 8);
                    ldmx4t(a[i], addr);
                } else {
                    uint32_t addr = smem_u32(as + (size_t)(mb + lr + (lq & 1) * 8) * SA
                                                + kk + (lq >> 1) * 8);
                    ldmx4(a[i], addr);
                }
            }
            #pragma unroll
            for (int jj = 0; jj < 2; jj++) {
                const int nb = wn + jj * 16;
                if (BTRANS) {
                    uint32_t addr = smem_u32(bs + (size_t)(nb + (lq >> 1) * 8 + lr) * SB
                                                + kk + (lq & 1) * 8);
                    ldmx4(b[jj], addr);
                } else {
                    uint32_t addr = smem_u32(bs + (size_t)(kk + (lq & 1) * 8 + lr) * SB
                                                + nb + (lq >> 1) * 8);
                    ldmx4t(b[jj], addr);
                }
            }
            #pragma unroll
            for (int i = 0; i < 4; i++)
                #pragma unroll
                for (int j = 0; j < 4; j++)
                    mma_f16(acc[i][j], a[i], &b[j >> 1][(j & 1) * 2]);
        }
    }

    __syncthreads();

    // ---- epilogue ----
    #pragma unroll
    for (int i = 0; i < 4; i++) {
        const int r0 = m0 + wm + i * 16 + gid;
        float b0v = 0.f, b1v = 0.f;
        if (HAS_BIAS) { b0v = Bi[r0]; b1v = Bi[r0 + 8]; }
        float rsum0 = 0.f, rsum1 = 0.f;
        #pragma unroll
        for (int j = 0; j < 4; j++) {
            const int c0 = n0 + wn + j * 8 + tig * 2;
            size_t i0 = (size_t)r0 * ldc + c0;
            size_t i1 = (size_t)(r0 + 8) * ldc + c0;
            float2 v0 = make_float2(acc[i][j][0], acc[i][j][1]);
            float2 v1 = make_float2(acc[i][j][2], acc[i][j][3]);
            if (HAS_BIAS) { v0.x += b0v; v0.y += b0v; v1.x += b1v; v1.y += b1v; }
            if (EPI == 2) {
                float2 r0v = *reinterpret_cast<const float2*>(&R[i0]);
                float2 r1v = *reinterpret_cast<const float2*>(&R[i1]);
                v0.x += r0v.x; v0.y += r0v.y; v1.x += r1v.x; v1.y += r1v.y;
            }
            if (EPI == 4) {
                v0.x = __expf(v0.x * scale); v0.y = __expf(v0.y * scale);
                v1.x = __expf(v1.x * scale); v1.y = __expf(v1.y * scale);
                rsum0 += v0.x + v0.y;
                rsum1 += v1.x + v1.y;
            }
            if (EPI == 5) {
                float l0 = L[c0], l1 = L[c0 + 1];
                v0.x /= l0; v0.y /= l1;
                v1.x /= l0; v1.y /= l1;
            }
            if (EPI == 2) {
                float* C = (float*)Cg + coff;
                *reinterpret_cast<float2*>(&C[i0]) = v0;
                *reinterpret_cast<float2*>(&C[i1]) = v1;
            } else {
                __half* C = (__half*)Cg + coff;
                *reinterpret_cast<__half2*>(&C[i0]) = __floats2half2_rn(v0.x, v0.y);
                *reinterpret_cast<__half2*>(&C[i1]) = __floats2half2_rn(v1.x, v1.y);
            }
        }
        if (EPI == 4) {
            rsum0 += __shfl_xor_sync(0xffffffffu, rsum0, 1);
            rsum0 += __shfl_xor_sync(0xffffffffu, rsum0, 2);
            rsum1 += __shfl_xor_sync(0xffffffffu, rsum1, 1);
            rsum1 += __shfl_xor_sync(0xffffffffu, rsum1, 2);
            if (tig == 0) {
                atomicAdd(&L[r0], rsum0);
                atomicAdd(&L[r0 + 8], rsum1);
            }
        }
    }
}

// ---------------- launch ----------------
extern "C" void kernel_launch(void* const* d_in, const int* in_sizes, int n_in,
                              void* d_out, int out_size) {
    const float* x        = (const float*)d_in[0];
    const float* gn_gamma = (const float*)d_in[1];
    const float* gn_beta  = (const float*)d_in[2];
    const float* wq       = (const float*)d_in[3];
    const float* bq       = (const float*)d_in[4];
    const float* wk       = (const float*)d_in[5];
    const float* bk       = (const float*)d_in[6];
    const float* wv       = (const float*)d_in[7];
    const float* bv       = (const float*)d_in[8];
    const float* wo       = (const float*)d_in[9];
    const float* bo       = (const float*)d_in[10];
    float* out = (float*)d_out;

    __half *ph, *pqkv, *po, *ps, *pw;
    float *pl, *pb, *pst;
    cudaGetSymbolAddress((void**)&ph, g_h);
    cudaGetSymbolAddress((void**)&pqkv, g_qkv);
    cudaGetSymbolAddress((void**)&po, g_o);
    cudaGetSymbolAddress((void**)&ps, g_s);
    cudaGetSymbolAddress((void**)&pl, g_l);
    cudaGetSymbolAddress((void**)&pw, g_w);
    cudaGetSymbolAddress((void**)&pb, g_bias);
    cudaGetSymbolAddress((void**)&pst, g_stats);

    const size_t sCH = (size_t)CH * HWN;
    const size_t sSS = (size_t)HWN * HWN;
    const float scale = 0.04419417382415922f; // 512^-0.5
    const int WS = CH * CH;
    __half* pq = pqkv;
    __half* pk = pqkv + (size_t)BATCH * sCH;
    __half* pv = pqkv + 2 * (size_t)BATCH * sCH;

    const int smem_ff = STAGES * (TM * (TK + 8) + TK * (TN + 8)) * 2;
    const int smem_tf = STAGES * (TK * (TM + 8) + TK * (TN + 8)) * 2;
    const int smem_ft = STAGES * (TM * (TK + 8) + TN * (TK + 8)) * 2;

    cudaFuncSetAttribute(gemm_f16<false, false, 6>, cudaFuncAttributeMaxDynamicSharedMemorySize, smem_ff);
    cudaFuncSetAttribute(gemm_f16<false, false, 2>, cudaFuncAttributeMaxDynamicSharedMemorySize, smem_ff);
    cudaFuncSetAttribute(gemm_f16<true,  false, 4>, cudaFuncAttributeMaxDynamicSharedMemorySize, smem_tf);
    cudaFuncSetAttribute(gemm_f16<false, true,  5>, cudaFuncAttributeMaxDynamicSharedMemorySize, smem_ft);

    // 0) weights/biases -> staged; zero row sums + stats
    cvt_w_kernel<<<256, 256>>>(wq, wk, wv, wo, bq, bk, bv, pw, pb);
    cudaMemsetAsync(pl, 0, (size_t)BATCH * HWN * sizeof(float));
    cudaMemsetAsync(pst, 0, (size_t)BATCH * NGROUPS * 2 * sizeof(float));

    // 1) GroupNorm: stats (1024 CTAs) then full-grid apply -> fp16 h
    gn_stats_kernel<<<BATCH * NGROUPS * 8, 256>>>(x, pst);
    gn_apply_kernel<<<(int)(BATCH * sCH / 4 / 256), 256>>>(x, gn_gamma, gn_beta, pst, ph);

    // 2) merged q,k,v projections: z = proj*4 + batch
    dim3 pg3(HWN / TN, CH / TM, 3 * BATCH);
    gemm_f16<false, false, 6><<<pg3, 256, smem_ff>>>(pw, ph, pqkv, pb, nullptr, nullptr,
        CH, CH, HWN, HWN, 0, sCH, sCH, 1.f);

    // 3) P~[n,m] = exp(scale * Q^T K) (fp16), row sums -> g_l
    dim3 sg(HWN / TN, HWN / TM, BATCH);
    gemm_f16<true, false, 4><<<sg, 256, smem_tf>>>(pq, pk, ps, nullptr, nullptr, pl,
        CH, HWN, HWN, HWN, sCH, sCH, sSS, scale);

    // 4) O[c,n] = (sum_m V[c,m] P~[n,m]) / l[n] (fp16)
    dim3 ag(HWN / TN, CH / TM, BATCH);
    gemm_f16<false, true, 5><<<ag, 256, smem_ft>>>(pv, ps, po, nullptr, nullptr, pl,
        HWN, HWN, HWN, HWN, sCH, sSS, sCH, 1.f);

    // 5) out projection + bias + residual (fp32 out)
    dim3 pg(HWN / TN, CH / TM, BATCH);
    gemm_f16<false, false, 2><<<pg, 256, smem_ff>>>(pw + 3 * WS, po, out, bo, x, nullptr,
        CH, CH, HWN, HWN, 0, sCH, sCH, 1.f);
}

// round 13
// speedup vs baseline: 1.5285x; 1.0390x over previous
#include <cuda_runtime.h>
#include <cuda_fp16.h>
#include <math.h>
#include <stdint.h>

#define BATCH 4
#define CH    512
#define HWN   4096
#define NGROUPS 32
#define CPG   16

#define TM 128
#define TN 128
#define TK 64
#define STAGES 3

// ---------------- scratch (device globals; allocation-free) ----------------
__device__ __half g_h[(size_t)BATCH * CH * HWN];
__device__ __half g_qkv[3 * (size_t)BATCH * CH * HWN];   // q,k,v contiguous
__device__ __half g_o[(size_t)BATCH * CH * HWN];
__device__ __half g_s[(size_t)BATCH * HWN * HWN];   // unnormalized exp(S)
__device__ float  g_l[(size_t)BATCH * HWN];         // row sums
__device__ __half g_w[4 * CH * CH];                 // fp16 weights q,k,v,o
__device__ float  g_bias[3 * CH];                   // staged biases q,k,v
__device__ float  g_stats[BATCH * NGROUPS * 2];     // GN sum / sumsq

// ---------------- helpers ----------------
__device__ __forceinline__ uint32_t smem_u32(const void* p) {
    return (uint32_t)__cvta_generic_to_shared(p);
}
__device__ __forceinline__ void cp16(uint32_t dst, const void* src) {
    asm volatile("cp.async.cg.shared.global [%0], [%1], 16;\n" :: "r"(dst), "l"(src));
}
__device__ __forceinline__ void cp_commit() {
    asm volatile("cp.async.commit_group;\n");
}
template<int N> __device__ __forceinline__ void cp_wait() {
    asm volatile("cp.async.wait_group %0;\n" :: "n"(N));
}
__device__ __forceinline__ void ldmx4(uint32_t* r, uint32_t a) {
    asm volatile("ldmatrix.sync.aligned.m8n8.x4.shared.b16 {%0,%1,%2,%3}, [%4];"
        : "=r"(r[0]), "=r"(r[1]), "=r"(r[2]), "=r"(r[3]) : "r"(a));
}
__device__ __forceinline__ void ldmx4t(uint32_t* r, uint32_t a) {
    asm volatile("ldmatrix.sync.aligned.m8n8.x4.trans.shared.b16 {%0,%1,%2,%3}, [%4];"
        : "=r"(r[0]), "=r"(r[1]), "=r"(r[2]), "=r"(r[3]) : "r"(a));
}
__device__ __forceinline__ void mma_f16(float* d, const uint32_t* a, const uint32_t* b) {
    asm volatile(
        "mma.sync.aligned.m16n8k16.row.col.f32.f16.f16.f32 "
        "{%0,%1,%2,%3}, {%4,%5,%6,%7}, {%8,%9}, {%0,%1,%2,%3};"
        : "+f"(d[0]), "+f"(d[1]), "+f"(d[2]), "+f"(d[3])
        : "r"(a[0]), "r"(a[1]), "r"(a[2]), "r"(a[3]), "r"(b[0]), "r"(b[1]));
}

// ---------------- weight/bias staging ----------------
__global__ void cvt_w_kernel(const float* __restrict__ w0, const float* __restrict__ w1,
                             const float* __restrict__ w2, const float* __restrict__ w3,
                             const float* __restrict__ b0, const float* __restrict__ b1,
                             const float* __restrict__ b2,
                             __half* __restrict__ dst, float* __restrict__ bdst) {
    const int n = CH * CH;
    const float* srcs[4] = {w0, w1, w2, w3};
    for (int idx = blockIdx.x * blockDim.x + threadIdx.x; idx < 4 * n;
         idx += gridDim.x * blockDim.x)
        dst[idx] = __float2half(srcs[idx / n][idx % n]);
    if (blockIdx.x == 0) {
        const float* bs[3] = {b0, b1, b2};
        for (int idx = threadIdx.x; idx < 3 * CH; idx += blockDim.x)
            bdst[idx] = bs[idx / CH][idx % CH];
    }
}

// ---------------- GroupNorm pass 1: partial stats -> atomics ---------------
__global__ void gn_stats_kernel(const float* __restrict__ x, float* __restrict__ stats) {
    const int bg   = blockIdx.x >> 3;
    const int part = blockIdx.x & 7;
    const float4* xp = reinterpret_cast<const float4*>(x) + (size_t)bg * 16384 + part * 2048;
    const int tid = threadIdx.x;

    float s = 0.f, ss = 0.f;
    #pragma unroll
    for (int i = 0; i < 8; i++) {
        float4 v = xp[tid + i * 256];
        s  += v.x + v.y + v.z + v.w;
        ss += v.x * v.x + v.y * v.y + v.z * v.z + v.w * v.w;
    }
    __shared__ float sh1[256], sh2[256];
    sh1[tid] = s; sh2[tid] = ss;
    __syncthreads();
    for (int o = 128; o > 0; o >>= 1) {
        if (tid < o) { sh1[tid] += sh1[tid + o]; sh2[tid] += sh2[tid + o]; }
        __syncthreads();
    }
    if (tid == 0) {
        atomicAdd(&stats[bg * 2],     sh1[0]);
        atomicAdd(&stats[bg * 2 + 1], sh2[0]);
    }
}

// ---------------- GroupNorm pass 2: normalize (fp32 in, fp16 out) ----------
__global__ void gn_apply_kernel(const float* __restrict__ x,
                                const float* __restrict__ gamma,
                                const float* __restrict__ beta,
                                const float* __restrict__ stats,
                                __half* __restrict__ h) {
    const size_t f = (size_t)blockIdx.x * blockDim.x + threadIdx.x;  // float4 index
    const int per_b = CH * HWN / 4;
    const int b = (int)(f / per_b);
    const int r = (int)(f % per_b);
    const int c = r / (HWN / 4);
    const int bg = b * NGROUPS + c / CPG;

    const float sum = stats[bg * 2], sumsq = stats[bg * 2 + 1];
    const float mean = sum * (1.f / 65536.f);
    const float var  = sumsq * (1.f / 65536.f) - mean * mean;
    const float inv  = rsqrtf(var + 1e-6f);
    const float sc = gamma[c] * inv;
    const float of = beta[c] - mean * sc;

    float4 v = reinterpret_cast<const float4*>(x)[f];
    __half2 h01 = __floats2half2_rn(v.x * sc + of, v.y * sc + of);
    __half2 h23 = __floats2half2_rn(v.z * sc + of, v.w * sc + of);
    uint2 pk;
    pk.x = *reinterpret_cast<uint32_t*>(&h01);
    pk.y = *reinterpret_cast<uint32_t*>(&h23);
    reinterpret_cast<uint2*>(h)[f] = pk;
}

// ---------------- FP16 tensor-core GEMM, 3-stage cp.async, TK=64 -----------
// C[m,n] = op(A)*op(B); ATRANS: A stored [K,M]; BTRANS: B stored [N,K]
// EPI: 2 +bias+res (float out), 4 exp+rowsum (half out),
//      5 col-normalize (half out), 6 merged QKV z=(proj,batch) +bias (half out)
template<bool ATRANS, bool BTRANS, int EPI>
__global__ __launch_bounds__(256, 2)
void gemm_f16(const __half* __restrict__ Ag, const __half* __restrict__ Bg,
              void* __restrict__ Cg,
              const float* __restrict__ bias, const float* __restrict__ res,
              float* __restrict__ Lsum,
              int K, int lda, int ldb, int ldc,
              size_t strA, size_t strB, size_t strC, float scale)
{
    extern __shared__ __half smem[];
    constexpr int SA = ATRANS ? (TM + 8) : (TK + 8);
    constexpr int SB = BTRANS ? (TK + 8) : (TN + 8);
    constexpr int SZA = ATRANS ? TK * SA : TM * SA;
    constexpr int SZB = BTRANS ? TN * SB : TK * SB;
    constexpr int STG = SZA + SZB;
    constexpr bool HAS_BIAS = (EPI == 2 || EPI == 6);
    constexpr int ACH = ATRANS ? TM / 8 : TK / 8;
    constexpr int ANR = ATRANS ? TK : TM;
    constexpr int BCH = BTRANS ? TK / 8 : TN / 8;
    constexpr int BNR = BTRANS ? TN : TK;

    const int zz = blockIdx.z;
    const int proj = (EPI == 6) ? (zz >> 2) : 0;
    const int bz   = (EPI == 6) ? (zz & 3)  : zz;
    const int m0 = blockIdx.y * TM;
    const int n0 = blockIdx.x * TN;
    const __half* A = Ag + ((EPI == 6) ? (size_t)proj * CH * CH : (size_t)bz * strA);
    const __half* B = Bg + (size_t)bz * strB;
    const size_t coff = (EPI == 6) ? ((size_t)proj * BATCH + bz) * strC
                                   : (size_t)bz * strC;
    const float* R = (EPI == 2) ? (res + coff) : nullptr;
    const float* Bi = HAS_BIAS ? (bias + ((EPI == 6) ? proj * CH : 0)) : nullptr;
    float* L = (EPI == 4 || EPI == 5) ? (Lsum + (size_t)bz * HWN) : nullptr;

    const int tid  = threadIdx.x;
    const int wid  = tid >> 5;
    const int lane = tid & 31;
    const int gid  = lane >> 2;
    const int tig  = lane & 3;
    const int wm   = (wid >> 2) * 64;
    const int wn   = (wid & 3) * 32;
    const int lq   = lane >> 3;
    const int lr   = lane & 7;

    auto copy_tile = [&](int kt, int st) {
        __half* as = smem + st * STG;
        __half* bs = as + SZA;
        const int k0 = kt * TK;
        #pragma unroll
        for (int i = 0; i < ANR * ACH / 256; i++) {
            int idx = tid + i * 256;
            int r = idx / ACH, c = idx % ACH;
            if (ATRANS)
                cp16(smem_u32(as + r * SA + c * 8), A + (size_t)(k0 + r) * lda + m0 + c * 8);
            else
                cp16(smem_u32(as + r * SA + c * 8), A + (size_t)(m0 + r) * lda + k0 + c * 8);
        }
        #pragma unroll
        for (int i = 0; i < BNR * BCH / 256; i++) {
            int idx = tid + i * 256;
            int r = idx / BCH, c = idx % BCH;
            if (BTRANS)
                cp16(smem_u32(bs + r * SB + c * 8), B + (size_t)(n0 + r) * ldb + k0 + c * 8);
            else
                cp16(smem_u32(bs + r * SB + c * 8), B + (size_t)(k0 + r) * ldb + n0 + c * 8);
        }
    };

    float acc[4][4][4] = {};
    const int KT = K / TK;

    copy_tile(0, 0); cp_commit();
    copy_tile(1, 1); cp_commit();

    for (int kt = 0; kt < KT; kt++) {
        cp_wait<1>();
        __syncthreads();
        if (kt + 2 < KT) copy_tile(kt + 2, (kt + 2) % STAGES);
        cp_commit();

        const __half* as = smem + (kt % STAGES) * STG;
        const __half* bs = as + SZA;

        #pragma unroll
        for (int ks = 0; ks < TK / 16; ks++) {
            const int kk = ks * 16;
            uint32_t a[4][4], b[2][4];
            #pragma unroll
            for (int i = 0; i < 4; i++) {
                const int mb = wm + i * 16;
                if (ATRANS)
                    ldmx4t(a[i], smem_u32(as + (size_t)(kk + (lq >> 1) * 8 + lr) * SA
                                             + mb + (lq & 1) * 8));
                else
                    ldmx4(a[i], smem_u32(as + (size_t)(mb + lr + (lq & 1) * 8) * SA
                                            + kk + (lq >> 1) * 8));
            }
            #pragma unroll
            for (int jj = 0; jj < 2; jj++) {
                const int nb = wn + jj * 16;
                if (BTRANS)
                    ldmx4(b[jj], smem_u32(bs + (size_t)(nb + (lq >> 1) * 8 + lr) * SB
                                             + kk + (lq & 1) * 8));
                else
                    ldmx4t(b[jj], smem_u32(bs + (size_t)(kk + (lq & 1) * 8 + lr) * SB
                                              + nb + (lq >> 1) * 8));
            }
            #pragma unroll
            for (int i = 0; i < 4; i++)
                #pragma unroll
                for (int j = 0; j < 4; j++)
                    mma_f16(acc[i][j], a[i], &b[j >> 1][(j & 1) * 2]);
        }
    }

    __syncthreads();

    // ---- epilogue ----
    #pragma unroll
    for (int i = 0; i < 4; i++) {
        const int r0 = m0 + wm + i * 16 + gid;
        float b0v = 0.f, b1v = 0.f;
        if (HAS_BIAS) { b0v = Bi[r0]; b1v = Bi[r0 + 8]; }
        float rsum0 = 0.f, rsum1 = 0.f;
        #pragma unroll
        for (int j = 0; j < 4; j++) {
            const int c0 = n0 + wn + j * 8 + tig * 2;
            size_t i0 = (size_t)r0 * ldc + c0;
            size_t i1 = (size_t)(r0 + 8) * ldc + c0;
            float2 v0 = make_float2(acc[i][j][0], acc[i][j][1]);
            float2 v1 = make_float2(acc[i][j][2], acc[i][j][3]);
            if (HAS_BIAS) { v0.x += b0v; v0.y += b0v; v1.x += b1v; v1.y += b1v; }
            if (EPI == 2) {
                float2 r0v = *reinterpret_cast<const float2*>(&R[i0]);
                float2 r1v = *reinterpret_cast<const float2*>(&R[i1]);
                v0.x += r0v.x; v0.y += r0v.y; v1.x += r1v.x; v1.y += r1v.y;
            }
            if (EPI == 4) {
                v0.x = __expf(v0.x * scale); v0.y = __expf(v0.y * scale);
                v1.x = __expf(v1.x * scale); v1.y = __expf(v1.y * scale);
                rsum0 += v0.x + v0.y;
                rsum1 += v1.x + v1.y;
            }
            if (EPI == 5) {
                float l0 = L[c0], l1 = L[c0 + 1];
                v0.x /= l0; v0.y /= l1;
                v1.x /= l0; v1.y /= l1;
            }
            if (EPI == 2) {
                float* C = (float*)Cg + coff;
                *reinterpret_cast<float2*>(&C[i0]) = v0;
                *reinterpret_cast<float2*>(&C[i1]) = v1;
            } else {
                __half* C = (__half*)Cg + coff;
                *reinterpret_cast<__half2*>(&C[i0]) = __floats2half2_rn(v0.x, v0.y);
                *reinterpret_cast<__half2*>(&C[i1]) = __floats2half2_rn(v1.x, v1.y);
            }
        }
        if (EPI == 4) {
            rsum0 += __shfl_xor_sync(0xffffffffu, rsum0, 1);
            rsum0 += __shfl_xor_sync(0xffffffffu, rsum0, 2);
            rsum1 += __shfl_xor_sync(0xffffffffu, rsum1, 1);
            rsum1 += __shfl_xor_sync(0xffffffffu, rsum1, 2);
            if (tig == 0) {
                atomicAdd(&L[r0], rsum0);
                atomicAdd(&L[r0 + 8], rsum1);
            }
        }
    }
}

// ---------------- launch ----------------
extern "C" void kernel_launch(void* const* d_in, const int* in_sizes, int n_in,
                              void* d_out, int out_size) {
    const float* x        = (const float*)d_in[0];
    const float* gn_gamma = (const float*)d_in[1];
    const float* gn_beta  = (const float*)d_in[2];
    const float* wq       = (const float*)d_in[3];
    const float* bq       = (const float*)d_in[4];
    const float* wk       = (const float*)d_in[5];
    const float* bk       = (const float*)d_in[6];
    const float* wv       = (const float*)d_in[7];
    const float* bv       = (const float*)d_in[8];
    const float* wo       = (const float*)d_in[9];
    const float* bo       = (const float*)d_in[10];
    float* out = (float*)d_out;

    __half *ph, *pqkv, *po, *ps, *pw;
    float *pl, *pb, *pst;
    cudaGetSymbolAddress((void**)&ph, g_h);
    cudaGetSymbolAddress((void**)&pqkv, g_qkv);
    cudaGetSymbolAddress((void**)&po, g_o);
    cudaGetSymbolAddress((void**)&ps, g_s);
    cudaGetSymbolAddress((void**)&pl, g_l);
    cudaGetSymbolAddress((void**)&pw, g_w);
    cudaGetSymbolAddress((void**)&pb, g_bias);
    cudaGetSymbolAddress((void**)&pst, g_stats);

    const size_t sCH = (size_t)CH * HWN;
    const size_t sSS = (size_t)HWN * HWN;
    const float scale = 0.04419417382415922f; // 512^-0.5
    const int WS = CH * CH;
    __half* pq = pqkv;
    __half* pk = pqkv + (size_t)BATCH * sCH;
    __half* pv = pqkv + 2 * (size_t)BATCH * sCH;

    const int smem_ff = STAGES * (TM * (TK + 8) + TK * (TN + 8)) * 2;
    const int smem_tf = STAGES * (TK * (TM + 8) + TK * (TN + 8)) * 2;
    const int smem_ft = STAGES * (TM * (TK + 8) + TN * (TK + 8)) * 2;

    cudaFuncSetAttribute(gemm_f16<false, false, 6>, cudaFuncAttributeMaxDynamicSharedMemorySize, smem_ff);
    cudaFuncSetAttribute(gemm_f16<false, false, 2>, cudaFuncAttributeMaxDynamicSharedMemorySize, smem_ff);
    cudaFuncSetAttribute(gemm_f16<true,  false, 4>, cudaFuncAttributeMaxDynamicSharedMemorySize, smem_tf);
    cudaFuncSetAttribute(gemm_f16<false, true,  5>, cudaFuncAttributeMaxDynamicSharedMemorySize, smem_ft);

    // 0) weights/biases -> staged; zero row sums + stats
    cvt_w_kernel<<<256, 256>>>(wq, wk, wv, wo, bq, bk, bv, pw, pb);
    cudaMemsetAsync(pl, 0, (size_t)BATCH * HWN * sizeof(float));
    cudaMemsetAsync(pst, 0, (size_t)BATCH * NGROUPS * 2 * sizeof(float));

    // 1) GroupNorm: stats then apply -> fp16 h
    gn_stats_kernel<<<BATCH * NGROUPS * 8, 256>>>(x, pst);
    gn_apply_kernel<<<(int)(BATCH * sCH / 4 / 256), 256>>>(x, gn_gamma, gn_beta, pst, ph);

    // 2) merged q,k,v projections: z = proj*4 + batch
    dim3 pg3(HWN / TN, CH / TM, 3 * BATCH);
    gemm_f16<false, false, 6><<<pg3, 256, smem_ff>>>(pw, ph, pqkv, pb, nullptr, nullptr,
        CH, CH, HWN, HWN, 0, sCH, sCH, 1.f);

    // 3) P~[n,m] = exp(scale * Q^T K) (fp16), row sums -> g_l
    dim3 sg(HWN / TN, HWN / TM, BATCH);
    gemm_f16<true, false, 4><<<sg, 256, smem_tf>>>(pq, pk, ps, nullptr, nullptr, pl,
        CH, HWN, HWN, HWN, sCH, sCH, sSS, scale);

    // 4) O[c,n] = (sum_m V[c,m] P~[n,m]) / l[n] (fp16)
    dim3 ag(HWN / TN, CH / TM, BATCH);
    gemm_f16<false, true, 5><<<ag, 256, smem_ft>>>(pv, ps, po, nullptr, nullptr, pl,
        HWN, HWN, HWN, HWN, sCH, sSS, sCH, 1.f);

    // 5) out projection + bias + residual (fp32 out)
    dim3 pg(HWN / TN, CH / TM, BATCH);
    gemm_f16<false, false, 2><<<pg, 256, smem_ff>>>(pw + 3 * WS, po, out, bo, x, nullptr,
        CH, CH, HWN, HWN, 0, sCH, sCH, 1.f);
}

// round 14
// speedup vs baseline: 1.5350x; 1.0043x over previous
#include <cuda_runtime.h>
#include <cuda_fp16.h>
#include <math.h>
#include <stdint.h>

#define BATCH 4
#define CH    512
#define HWN   4096
#define NGROUPS 32
#define CPG   16

#define TM 128
#define TN 128
#define TK 64
#define STAGES 3

// ---------------- scratch (device globals; allocation-free) ----------------
__device__ __half g_h[(size_t)BATCH * CH * HWN];
__device__ __half g_qkv[3 * (size_t)BATCH * CH * HWN];   // q,k,v contiguous
__device__ __half g_o[(size_t)BATCH * CH * HWN];
__device__ __half g_s[(size_t)BATCH * HWN * HWN];   // unnormalized exp(S)
__device__ float  g_l[(size_t)BATCH * HWN];         // row sums
__device__ __half g_w[4 * CH * CH];                 // fp16 weights q,k,v,o
__device__ float  g_bias[3 * CH];                   // staged biases q,k,v
__device__ float  g_stats[BATCH * NGROUPS * 2];     // GN sum / sumsq

// ---------------- helpers ----------------
__device__ __forceinline__ uint32_t smem_u32(const void* p) {
    return (uint32_t)__cvta_generic_to_shared(p);
}
__device__ __forceinline__ void cp16(uint32_t dst, const void* src) {
    asm volatile("cp.async.cg.shared.global [%0], [%1], 16;\n" :: "r"(dst), "l"(src));
}
__device__ __forceinline__ void cp_commit() {
    asm volatile("cp.async.commit_group;\n");
}
template<int N> __device__ __forceinline__ void cp_wait() {
    asm volatile("cp.async.wait_group %0;\n" :: "n"(N));
}
__device__ __forceinline__ void ldmx4(uint32_t* r, uint32_t a) {
    asm volatile("ldmatrix.sync.aligned.m8n8.x4.shared.b16 {%0,%1,%2,%3}, [%4];"
        : "=r"(r[0]), "=r"(r[1]), "=r"(r[2]), "=r"(r[3]) : "r"(a));
}
__device__ __forceinline__ void ldmx4t(uint32_t* r, uint32_t a) {
    asm volatile("ldmatrix.sync.aligned.m8n8.x4.trans.shared.b16 {%0,%1,%2,%3}, [%4];"
        : "=r"(r[0]), "=r"(r[1]), "=r"(r[2]), "=r"(r[3]) : "r"(a));
}
__device__ __forceinline__ void mma_f16(float* d, const uint32_t* a, const uint32_t* b) {
    asm volatile(
        "mma.sync.aligned.m16n8k16.row.col.f32.f16.f16.f32 "
        "{%0,%1,%2,%3}, {%4,%5,%6,%7}, {%8,%9}, {%0,%1,%2,%3};"
        : "+f"(d[0]), "+f"(d[1]), "+f"(d[2]), "+f"(d[3])
        : "r"(a[0]), "r"(a[1]), "r"(a[2]), "r"(a[3]), "r"(b[0]), "r"(b[1]));
}
// fp16-accumulate HMMA (probe: may be double-rate on sm_103a legacy pipe)
__device__ __forceinline__ void mma_f16h(uint32_t* d, const uint32_t* a, const uint32_t* b) {
    asm volatile(
        "mma.sync.aligned.m16n8k16.row.col.f16.f16.f16.f16 "
        "{%0,%1}, {%2,%3,%4,%5}, {%6,%7}, {%0,%1};"
        : "+r"(d[0]), "+r"(d[1])
        : "r"(a[0]), "r"(a[1]), "r"(a[2]), "r"(a[3]), "r"(b[0]), "r"(b[1]));
}

// ---------------- weight/bias staging ----------------
__global__ void cvt_w_kernel(const float* __restrict__ w0, const float* __restrict__ w1,
                             const float* __restrict__ w2, const float* __restrict__ w3,
                             const float* __restrict__ b0, const float* __restrict__ b1,
                             const float* __restrict__ b2,
                             __half* __restrict__ dst, float* __restrict__ bdst) {
    const int n = CH * CH;
    const float* srcs[4] = {w0, w1, w2, w3};
    for (int idx = blockIdx.x * blockDim.x + threadIdx.x; idx < 4 * n;
         idx += gridDim.x * blockDim.x)
        dst[idx] = __float2half(srcs[idx / n][idx % n]);
    if (blockIdx.x == 0) {
        const float* bs[3] = {b0, b1, b2};
        for (int idx = threadIdx.x; idx < 3 * CH; idx += blockDim.x)
            bdst[idx] = bs[idx / CH][idx % CH];
    }
}

// ---------------- GroupNorm pass 1: partial stats -> atomics ---------------
__global__ void gn_stats_kernel(const float* __restrict__ x, float* __restrict__ stats) {
    const int bg   = blockIdx.x >> 3;
    const int part = blockIdx.x & 7;
    const float4* xp = reinterpret_cast<const float4*>(x) + (size_t)bg * 16384 + part * 2048;
    const int tid = threadIdx.x;

    float s = 0.f, ss = 0.f;
    #pragma unroll
    for (int i = 0; i < 8; i++) {
        float4 v = xp[tid + i * 256];
        s  += v.x + v.y + v.z + v.w;
        ss += v.x * v.x + v.y * v.y + v.z * v.z + v.w * v.w;
    }
    __shared__ float sh1[256], sh2[256];
    sh1[tid] = s; sh2[tid] = ss;
    __syncthreads();
    for (int o = 128; o > 0; o >>= 1) {
        if (tid < o) { sh1[tid] += sh1[tid + o]; sh2[tid] += sh2[tid + o]; }
        __syncthreads();
    }
    if (tid == 0) {
        atomicAdd(&stats[bg * 2],     sh1[0]);
        atomicAdd(&stats[bg * 2 + 1], sh2[0]);
    }
}

// ---------------- GroupNorm pass 2: normalize (fp32 in, fp16 out) ----------
__global__ void gn_apply_kernel(const float* __restrict__ x,
                                const float* __restrict__ gamma,
                                const float* __restrict__ beta,
                                const float* __restrict__ stats,
                                __half* __restrict__ h) {
    const size_t f = (size_t)blockIdx.x * blockDim.x + threadIdx.x;  // float4 index
    const int per_b = CH * HWN / 4;
    const int b = (int)(f / per_b);
    const int r = (int)(f % per_b);
    const int c = r / (HWN / 4);
    const int bg = b * NGROUPS + c / CPG;

    const float sum = stats[bg * 2], sumsq = stats[bg * 2 + 1];
    const float mean = sum * (1.f / 65536.f);
    const float var  = sumsq * (1.f / 65536.f) - mean * mean;
    const float inv  = rsqrtf(var + 1e-6f);
    const float sc = gamma[c] * inv;
    const float of = beta[c] - mean * sc;

    float4 v = reinterpret_cast<const float4*>(x)[f];
    __half2 h01 = __floats2half2_rn(v.x * sc + of, v.y * sc + of);
    __half2 h23 = __floats2half2_rn(v.z * sc + of, v.w * sc + of);
    uint2 pk;
    pk.x = *reinterpret_cast<uint32_t*>(&h01);
    pk.y = *reinterpret_cast<uint32_t*>(&h23);
    reinterpret_cast<uint2*>(h)[f] = pk;
}

// ---------------- FP16 tensor-core GEMM, 3-stage cp.async, TK=64 -----------
// C[m,n] = op(A)*op(B); ATRANS: A stored [K,M]; BTRANS: B stored [N,K]
// EPI: 2 +bias+res (float out, f32 acc), 6 merged QKV +bias (half out, f32 acc),
//      4 exp+rowsum (half out, F16 ACC), 5 col-normalize (half out, F16 ACC)
template<bool ATRANS, bool BTRANS, int EPI>
__global__ __launch_bounds__(256, 2)
void gemm_f16(const __half* __restrict__ Ag, const __half* __restrict__ Bg,
              void* __restrict__ Cg,
              const float* __restrict__ bias, const float* __restrict__ res,
              float* __restrict__ Lsum,
              int K, int lda, int ldb, int ldc,
              size_t strA, size_t strB, size_t strC, float scale)
{
    extern __shared__ __half smem[];
    constexpr int SA = ATRANS ? (TM + 8) : (TK + 8);
    constexpr int SB = BTRANS ? (TK + 8) : (TN + 8);
    constexpr int SZA = ATRANS ? TK * SA : TM * SA;
    constexpr int SZB = BTRANS ? TN * SB : TK * SB;
    constexpr int STG = SZA + SZB;
    constexpr bool HAS_BIAS = (EPI == 2 || EPI == 6);
    constexpr bool F16ACC = (EPI == 4 || EPI == 5);
    constexpr int ACH = ATRANS ? TM / 8 : TK / 8;
    constexpr int ANR = ATRANS ? TK : TM;
    constexpr int BCH = BTRANS ? TK / 8 : TN / 8;
    constexpr int BNR = BTRANS ? TN : TK;

    const int zz = blockIdx.z;
    const int proj = (EPI == 6) ? (zz >> 2) : 0;
    const int bz   = (EPI == 6) ? (zz & 3)  : zz;
    const int m0 = blockIdx.y * TM;
    const int n0 = blockIdx.x * TN;
    const __half* A = Ag + ((EPI == 6) ? (size_t)proj * CH * CH : (size_t)bz * strA);
    const __half* B = Bg + (size_t)bz * strB;
    const size_t coff = (EPI == 6) ? ((size_t)proj * BATCH + bz) * strC
                                   : (size_t)bz * strC;
    const float* R = (EPI == 2) ? (res + coff) : nullptr;
    const float* Bi = HAS_BIAS ? (bias + ((EPI == 6) ? proj * CH : 0)) : nullptr;
    float* L = (EPI == 4 || EPI == 5) ? (Lsum + (size_t)bz * HWN) : nullptr;

    const int tid  = threadIdx.x;
    const int wid  = tid >> 5;
    const int lane = tid & 31;
    const int gid  = lane >> 2;
    const int tig  = lane & 3;
    const int wm   = (wid >> 2) * 64;
    const int wn   = (wid & 3) * 32;
    const int lq   = lane >> 3;
    const int lr   = lane & 7;

    auto copy_tile = [&](int kt, int st) {
        __half* as = smem + st * STG;
        __half* bs = as + SZA;
        const int k0 = kt * TK;
        #pragma unroll
        for (int i = 0; i < ANR * ACH / 256; i++) {
            int idx = tid + i * 256;
            int r = idx / ACH, c = idx % ACH;
            if (ATRANS)
                cp16(smem_u32(as + r * SA + c * 8), A + (size_t)(k0 + r) * lda + m0 + c * 8);
            else
                cp16(smem_u32(as + r * SA + c * 8), A + (size_t)(m0 + r) * lda + k0 + c * 8);
        }
        #pragma unroll
        for (int i = 0; i < BNR * BCH / 256; i++) {
            int idx = tid + i * 256;
            int r = idx / BCH, c = idx % BCH;
            if (BTRANS)
                cp16(smem_u32(bs + r * SB + c * 8), B + (size_t)(n0 + r) * ldb + k0 + c * 8);
            else
                cp16(smem_u32(bs + r * SB + c * 8), B + (size_t)(k0 + r) * ldb + n0 + c * 8);
        }
    };

    float    accf[4][4][4] = {};
    uint32_t acch[4][4][2] = {};
    const int KT = K / TK;

    copy_tile(0, 0); cp_commit();
    copy_tile(1, 1); cp_commit();

    for (int kt = 0; kt < KT; kt++) {
        cp_wait<1>();
        __syncthreads();
        if (kt + 2 < KT) copy_tile(kt + 2, (kt + 2) % STAGES);
        cp_commit();

        const __half* as = smem + (kt % STAGES) * STG;
        const __half* bs = as + SZA;

        #pragma unroll
        for (int ks = 0; ks < TK / 16; ks++) {
            const int kk = ks * 16;
            uint32_t a[4][4], b[2][4];
            #pragma unroll
            for (int i = 0; i < 4; i++) {
                const int mb = wm + i * 16;
                if (ATRANS)
                    ldmx4t(a[i], smem_u32(as + (size_t)(kk + (lq >> 1) * 8 + lr) * SA
                                             + mb + (lq & 1) * 8));
                else
                    ldmx4(a[i], smem_u32(as + (size_t)(mb + lr + (lq & 1) * 8) * SA
                                            + kk + (lq >> 1) * 8));
            }
            #pragma unroll
            for (int jj = 0; jj < 2; jj++) {
                const int nb = wn + jj * 16;
                if (BTRANS)
                    ldmx4(b[jj], smem_u32(bs + (size_t)(nb + (lq >> 1) * 8 + lr) * SB
                                             + kk + (lq & 1) * 8));
                else
                    ldmx4t(b[jj], smem_u32(bs + (size_t)(kk + (lq & 1) * 8 + lr) * SB
                                              + nb + (lq >> 1) * 8));
            }
            #pragma unroll
            for (int i = 0; i < 4; i++)
                #pragma unroll
                for (int j = 0; j < 4; j++) {
                    if (F16ACC) mma_f16h(acch[i][j], a[i], &b[j >> 1][(j & 1) * 2]);
                    else        mma_f16 (accf[i][j], a[i], &b[j >> 1][(j & 1) * 2]);
                }
        }
    }

    __syncthreads();

    // ---- epilogue ----
    #pragma unroll
    for (int i = 0; i < 4; i++) {
        const int r0 = m0 + wm + i * 16 + gid;
        float b0v = 0.f, b1v = 0.f;
        if (HAS_BIAS) { b0v = Bi[r0]; b1v = Bi[r0 + 8]; }
        float rsum0 = 0.f, rsum1 = 0.f;
        #pragma unroll
        for (int j = 0; j < 4; j++) {
            const int c0 = n0 + wn + j * 8 + tig * 2;
            size_t i0 = (size_t)r0 * ldc + c0;
            size_t i1 = (size_t)(r0 + 8) * ldc + c0;
            float2 v0, v1;
            if (F16ACC) {
                __half2 p0 = *reinterpret_cast<__half2*>(&acch[i][j][0]);
                __half2 p1 = *reinterpret_cast<__half2*>(&acch[i][j][1]);
                v0 = __half22float2(p0);
                v1 = __half22float2(p1);
            } else {
                v0 = make_float2(accf[i][j][0], accf[i][j][1]);
                v1 = make_float2(accf[i][j][2], accf[i][j][3]);
            }
            if (HAS_BIAS) { v0.x += b0v; v0.y += b0v; v1.x += b1v; v1.y += b1v; }
            if (EPI == 2) {
                float2 r0v = *reinterpret_cast<const float2*>(&R[i0]);
                float2 r1v = *reinterpret_cast<const float2*>(&R[i1]);
                v0.x += r0v.x; v0.y += r0v.y; v1.x += r1v.x; v1.y += r1v.y;
            }
            if (EPI == 4) {
                v0.x = __expf(v0.x * scale); v0.y = __expf(v0.y * scale);
                v1.x = __expf(v1.x * scale); v1.y = __expf(v1.y * scale);
                rsum0 += v0.x + v0.y;
                rsum1 += v1.x + v1.y;
            }
            if (EPI == 5) {
                float l0 = L[c0], l1 = L[c0 + 1];
                v0.x /= l0; v0.y /= l1;
                v1.x /= l0; v1.y /= l1;
            }
            if (EPI == 2) {
                float* C = (float*)Cg + coff;
                *reinterpret_cast<float2*>(&C[i0]) = v0;
                *reinterpret_cast<float2*>(&C[i1]) = v1;
            } else {
                __half* C = (__half*)Cg + coff;
                *reinterpret_cast<__half2*>(&C[i0]) = __floats2half2_rn(v0.x, v0.y);
                *reinterpret_cast<__half2*>(&C[i1]) = __floats2half2_rn(v1.x, v1.y);
            }
        }
        if (EPI == 4) {
            rsum0 += __shfl_xor_sync(0xffffffffu, rsum0, 1);
            rsum0 += __shfl_xor_sync(0xffffffffu, rsum0, 2);
            rsum1 += __shfl_xor_sync(0xffffffffu, rsum1, 1);
            rsum1 += __shfl_xor_sync(0xffffffffu, rsum1, 2);
            if (tig == 0) {
                atomicAdd(&L[r0], rsum0);
                atomicAdd(&L[r0 + 8], rsum1);
            }
        }
    }
}

// ---------------- launch ----------------
extern "C" void kernel_launch(void* const* d_in, const int* in_sizes, int n_in,
                              void* d_out, int out_size) {
    const float* x        = (const float*)d_in[0];
    const float* gn_gamma = (const float*)d_in[1];
    const float* gn_beta  = (const float*)d_in[2];
    const float* wq       = (const float*)d_in[3];
    const float* bq       = (const float*)d_in[4];
    const float* wk       = (const float*)d_in[5];
    const float* bk       = (const float*)d_in[6];
    const float* wv       = (const float*)d_in[7];
    const float* bv       = (const float*)d_in[8];
    const float* wo       = (const float*)d_in[9];
    const float* bo       = (const float*)d_in[10];
    float* out = (float*)d_out;

    __half *ph, *pqkv, *po, *ps, *pw;
    float *pl, *pb, *pst;
    cudaGetSymbolAddress((void**)&ph, g_h);
    cudaGetSymbolAddress((void**)&pqkv, g_qkv);
    cudaGetSymbolAddress((void**)&po, g_o);
    cudaGetSymbolAddress((void**)&ps, g_s);
    cudaGetSymbolAddress((void**)&pl, g_l);
    cudaGetSymbolAddress((void**)&pw, g_w);
    cudaGetSymbolAddress((void**)&pb, g_bias);
    cudaGetSymbolAddress((void**)&pst, g_stats);

    const size_t sCH = (size_t)CH * HWN;
    const size_t sSS = (size_t)HWN * HWN;
    const float scale = 0.04419417382415922f; // 512^-0.5
    const int WS = CH * CH;
    __half* pq = pqkv;
    __half* pk = pqkv + (size_t)BATCH * sCH;
    __half* pv = pqkv + 2 * (size_t)BATCH * sCH;

    const int smem_ff = STAGES * (TM * (TK + 8) + TK * (TN + 8)) * 2;
    const int smem_tf = STAGES * (TK * (TM + 8) + TK * (TN + 8)) * 2;
    const int smem_ft = STAGES * (TM * (TK + 8) + TN * (TK + 8)) * 2;

    cudaFuncSetAttribute(gemm_f16<false, false, 6>, cudaFuncAttributeMaxDynamicSharedMemorySize, smem_ff);
    cudaFuncSetAttribute(gemm_f16<false, false, 2>, cudaFuncAttributeMaxDynamicSharedMemorySize, smem_ff);
    cudaFuncSetAttribute(gemm_f16<true,  false, 4>, cudaFuncAttributeMaxDynamicSharedMemorySize, smem_tf);
    cudaFuncSetAttribute(gemm_f16<false, true,  5>, cudaFuncAttributeMaxDynamicSharedMemorySize, smem_ft);

    // 0) weights/biases -> staged; zero row sums + stats
    cvt_w_kernel<<<256, 256>>>(wq, wk, wv, wo, bq, bk, bv, pw, pb);
    cudaMemsetAsync(pl, 0, (size_t)BATCH * HWN * sizeof(float));
    cudaMemsetAsync(pst, 0, (size_t)BATCH * NGROUPS * 2 * sizeof(float));

    // 1) GroupNorm: stats then apply -> fp16 h
    gn_stats_kernel<<<BATCH * NGROUPS * 8, 256>>>(x, pst);
    gn_apply_kernel<<<(int)(BATCH * sCH / 4 / 256), 256>>>(x, gn_gamma, gn_beta, pst, ph);

    // 2) merged q,k,v projections: z = proj*4 + batch
    dim3 pg3(HWN / TN, CH / TM, 3 * BATCH);
    gemm_f16<false, false, 6><<<pg3, 256, smem_ff>>>(pw, ph, pqkv, pb, nullptr, nullptr,
        CH, CH, HWN, HWN, 0, sCH, sCH, 1.f);

    // 3) P~[n,m] = exp(scale * Q^T K) (fp16), row sums -> g_l  [f16 acc probe]
    dim3 sg(HWN / TN, HWN / TM, BATCH);
    gemm_f16<true, false, 4><<<sg, 256, smem_tf>>>(pq, pk, ps, nullptr, nullptr, pl,
        CH, HWN, HWN, HWN, sCH, sCH, sSS, scale);

    // 4) O[c,n] = (sum_m V[c,m] P~[n,m]) / l[n] (fp16)  [f16 acc probe]
    dim3 ag(HWN / TN, CH / TM, BATCH);
    gemm_f16<false, true, 5><<<ag, 256, smem_ft>>>(pv, ps, po, nullptr, nullptr, pl,
        HWN, HWN, HWN, HWN, sCH, sSS, sCH, 1.f);

    // 5) out projection + bias + residual (fp32 out)
    dim3 pg(HWN / TN, CH / TM, BATCH);
    gemm_f16<false, false, 2><<<pg, 256, smem_ff>>>(pw + 3 * WS, po, out, bo, x, nullptr,
        CH, CH, HWN, HWN, 0, sCH, sCH, 1.f);
}